// round 3
// baseline (speedup 1.0000x reference)
#include <cuda_runtime.h>
#include <cstdint>
#include <math.h>

// Problem dims
#define BB 64
#define HH 1024
#define SS 128
#define VV 32000
#define KX 2048        // E + H
#define G4 4096        // 4*H
#define KSPLIT 6

// d_out layout (floats)
#define OUT_H1   (64*32000)
#define OUT_C1   (OUT_H1 + 64*1024)
#define OUT_ATTN (OUT_C1 + 64*1024)

// Scratch (no allocation allowed -> device globals)
__device__ __align__(16) float g_xT [KX*BB];          // x^T   (2048 x 64): rows 0..1023 emb, 1024..2047 context
__device__ __align__(16) float g_h0T[HH*BB];          // h0^T  (1024 x 64)
__device__ __align__(16) float g_h1T[HH*BB];          // h1^T  (1024 x 64)
__device__ __align__(16) float g_part[KSPLIT*G4*BB];  // gates K-split partials

typedef unsigned long long ull;
__device__ __forceinline__ ull pk2(float x, float y){
    ull r; asm("mov.b64 %0, {%1, %2};" : "=l"(r) : "f"(x), "f"(y)); return r;
}
__device__ __forceinline__ void upk2(ull v, float& x, float& y){
    asm("mov.b64 {%0, %1}, %2;" : "=f"(x), "=f"(y) : "l"(v));
}
__device__ __forceinline__ void ffma2(ull& acc, ull a, ull b){
    asm("fma.rn.f32x2 %0, %1, %2, %0;" : "+l"(acc) : "l"(a), "l"(b));
}

// ---------------------------------------------------------------------------
// Kernel 1: attention (scores, softmax, context) + emb gather + transposes
// grid: 64 blocks (one per batch), 256 threads
// ---------------------------------------------------------------------------
__global__ void attn_kernel(const int* __restrict__ input_batch, const float* __restrict__ prev_h,
                            const float* __restrict__ enc, const float* __restrict__ emb,
                            const float* __restrict__ attn_w, const float* __restrict__ attn_b,
                            float* __restrict__ out)
{
    __shared__ float sw2[1024];
    __shared__ float sweights[128];
    __shared__ float red[40];
    const int b = blockIdx.x, tid = threadIdx.x, lane = tid & 31, warp = tid >> 5;
    const int tok = input_batch[b];

    float hacc = 0.f;
    for (int i = tid; i < 1024; i += 256){
        float h0v = prev_h[(size_t)b*1024 + i];
        hacc += attn_w[i] * h0v;
        sw2[i] = attn_w[1024 + i];
        g_h0T[(size_t)i*64 + b] = h0v;
        g_xT [(size_t)i*64 + b] = emb[(size_t)tok*1024 + i];
    }
    #pragma unroll
    for (int o=16;o;o>>=1) hacc += __shfl_xor_sync(0xffffffffu, hacc, o);
    if (lane==0) red[warp] = hacc;
    __syncthreads();
    if (tid==0){ float s=0.f; for (int w=0;w<8;w++) s+=red[w]; red[32] = s + attn_b[0]; }
    __syncthreads();
    const float hpb = red[32];

    const float* encb = enc + (size_t)b*SS*HH;
    for (int s = warp; s < 128; s += 8){
        const float* ep = encb + (size_t)s*1024;
        float acc = 0.f;
        #pragma unroll 8
        for (int j=0;j<32;j++){ int i = lane + j*32; acc += ep[i]*sw2[i]; }
        #pragma unroll
        for (int o=16;o;o>>=1) acc += __shfl_xor_sync(0xffffffffu, acc, o);
        if (lane==0) sweights[s] = acc + hpb;
    }
    __syncthreads();

    // softmax over 128 scores
    float sc = (tid<128) ? sweights[tid] : -3.0e38f;
    float m = sc;
    #pragma unroll
    for (int o=16;o;o>>=1) m = fmaxf(m, __shfl_xor_sync(0xffffffffu, m, o));
    if (lane==0) red[warp] = m;
    __syncthreads();
    if (tid==0){ float mm=red[0]; for (int w=1;w<8;w++) mm=fmaxf(mm,red[w]); red[33]=mm; }
    __syncthreads();
    m = red[33];
    float e = (tid<128) ? __expf(sc - m) : 0.f;
    float z = e;
    #pragma unroll
    for (int o=16;o;o>>=1) z += __shfl_xor_sync(0xffffffffu, z, o);
    if (lane==0) red[warp] = z;
    __syncthreads();
    if (tid==0){ float s=0.f; for (int w=0;w<8;w++) s+=red[w]; red[34]=s; }
    __syncthreads();
    const float Z = red[34];
    if (tid < 128){
        float w = e / Z;
        sweights[tid] = w;
        out[OUT_ATTN + b*128 + tid] = w;
    }
    __syncthreads();

    // context: each thread 4 consecutive h (float4), 2nd pass over encoder (L2-hot)
    const int h4 = tid*4;
    float4 a4 = {0.f,0.f,0.f,0.f};
    for (int s=0;s<128;s++){
        float w = sweights[s];
        float4 ev = *(const float4*)(encb + (size_t)s*1024 + h4);
        a4.x += w*ev.x; a4.y += w*ev.y; a4.z += w*ev.z; a4.w += w*ev.w;
    }
    g_xT[(size_t)(1024+h4+0)*64 + b] = a4.x;
    g_xT[(size_t)(1024+h4+1)*64 + b] = a4.y;
    g_xT[(size_t)(1024+h4+2)*64 + b] = a4.z;
    g_xT[(size_t)(1024+h4+3)*64 + b] = a4.w;
}

// ---------------------------------------------------------------------------
// Kernel 2: gates GEMM  gatesT[4096][64] += W[g,:] . xcat[:,b], K-split x 6
// grid (32, 6), 256 threads. Tile 128x64, BK=16, FFMA2 inner product.
// ---------------------------------------------------------------------------
__global__ __launch_bounds__(256,2) void gates_gemm(const float* __restrict__ W_ih,
                                                    const float* __restrict__ W_hh)
{
    __shared__ __align__(16) float As[128][20];
    __shared__ __align__(16) float Bs[16][64];
    const int tid = threadIdx.x;
    const int g0 = blockIdx.x * 128;
    const int ky = blockIdx.y;
    const int kbase = ky * 512;
    const bool ih = (ky < 4);
    const int lda = ih ? KX : HH;
    const float* A  = ih ? (W_ih + (size_t)g0*KX + kbase)
                         : (W_hh + (size_t)g0*HH + (kbase - KX));
    const float* Bp = ih ? (g_xT + (size_t)kbase*64)
                         : (g_h0T + (size_t)(kbase - KX)*64);

    const int ar = tid>>1, ac = (tid&1)*8;
    const int bk = tid>>4, bn = (tid&15)*4;
    const int v0 = (tid>>4)*8, n0 = (tid&15)*4;

    ull acc[8][2];
    #pragma unroll
    for (int j=0;j<8;j++){ acc[j][0]=0ull; acc[j][1]=0ull; }

    float4 pa0 = *(const float4*)(A + (size_t)ar*lda + ac);
    float4 pa1 = *(const float4*)(A + (size_t)ar*lda + ac + 4);
    float4 pb  = *(const float4*)(Bp + bk*64 + bn);

    const int NT = 512/16;
    for (int t=0; t<NT; ++t){
        *(float4*)&As[ar][ac]   = pa0;
        *(float4*)&As[ar][ac+4] = pa1;
        *(float4*)&Bs[bk][bn]   = pb;
        __syncthreads();
        if (t+1 < NT){
            const float* An = A + (t+1)*16;
            pa0 = *(const float4*)(An + (size_t)ar*lda + ac);
            pa1 = *(const float4*)(An + (size_t)ar*lda + ac + 4);
            pb  = *(const float4*)(Bp + (size_t)((t+1)*16 + bk)*64 + bn);
        }
        #pragma unroll
        for (int kq=0; kq<4; ++kq){
            float4 av[8];
            #pragma unroll
            for (int j=0;j<8;j++) av[j] = *(const float4*)&As[v0+j][kq*4];
            float4 bv[4];
            #pragma unroll
            for (int kk=0;kk<4;kk++) bv[kk] = *(const float4*)&Bs[kq*4+kk][n0];
            #pragma unroll
            for (int kk=0;kk<4;kk++){
                ull b01 = pk2(((const float*)&bv[kk])[0], ((const float*)&bv[kk])[1]);
                ull b23 = pk2(((const float*)&bv[kk])[2], ((const float*)&bv[kk])[3]);
                #pragma unroll
                for (int j=0;j<8;j++){
                    float a = ((const float*)&av[j])[kk];
                    ull aa = pk2(a, a);
                    ffma2(acc[j][0], aa, b01);
                    ffma2(acc[j][1], aa, b23);
                }
            }
        }
        __syncthreads();
    }
    float* P = g_part + ((size_t)ky*G4 + g0)*64;
    #pragma unroll
    for (int j=0;j<8;j++){
        float4 o;
        upk2(acc[j][0], o.x, o.y);
        upk2(acc[j][1], o.z, o.w);
        *(float4*)&P[(size_t)(v0+j)*64 + n0] = o;
    }
}

// ---------------------------------------------------------------------------
// Kernel 3: K-split reduce + biases + LSTM cell. 256 blocks x 256 threads.
// ---------------------------------------------------------------------------
__global__ void lstm_kernel(const float* __restrict__ prev_c, const int* __restrict__ lengths,
                            const float* __restrict__ b_ih, const float* __restrict__ b_hh,
                            float* __restrict__ out)
{
    const int id = blockIdx.x*256 + threadIdx.x;   // 0..65535
    const int b = id & 63, h = id >> 6;
    float s[4] = {0.f,0.f,0.f,0.f};
    #pragma unroll
    for (int ky=0; ky<KSPLIT; ++ky){
        const float* P = g_part + (size_t)ky*G4*64;
        #pragma unroll
        for (int g=0; g<4; ++g) s[g] += P[(size_t)(g*1024 + h)*64 + b];
    }
    #pragma unroll
    for (int g=0; g<4; ++g) s[g] += b_ih[g*1024+h] + b_hh[g*1024+h];
    float ig = 1.f/(1.f + __expf(-s[0]));
    float fg = 1.f/(1.f + __expf(-s[1]));
    float gg = tanhf(s[2]);
    float og = 1.f/(1.f + __expf(-s[3]));
    float c0 = prev_c[(size_t)b*HH + h];
    float c1 = fg*c0 + ig*gg;
    float h1 = og*tanhf(c1);
    if (lengths[b] == 0){ c1 = 0.f; h1 = 0.f; }
    out[OUT_H1 + b*HH + h] = h1;
    out[OUT_C1 + b*HH + h] = c1;
    g_h1T[(size_t)h*64 + b] = h1;
}

// ---------------------------------------------------------------------------
// Kernel 4: logits GEMM  out[b][v] = h1[b,:].W_out[v,:] + b_out[v]
// grid 250, 256 threads. Tile 128x64, BK=16, smem-transposed epilogue.
// ---------------------------------------------------------------------------
__global__ __launch_bounds__(256,2) void logits_gemm(const float* __restrict__ W_out,
                                                     const float* __restrict__ b_out,
                                                     float* __restrict__ out)
{
    __shared__ __align__(16) float smemc[8192];                 // 32KB, aliased
    float (*As)[20] = (float(*)[20])smemc;                      // 128*20 = 2560 floats
    float (*Bs)[64] = (float(*)[64])(smemc + 128*20);           // 16*64  = 1024 floats
    const int tid = threadIdx.x;
    const int vb = blockIdx.x * 128;
    const float* A  = W_out + (size_t)vb * HH;
    const float* Bp = g_h1T;

    const int ar = tid>>1, ac = (tid&1)*8;
    const int bk = tid>>4, bn = (tid&15)*4;
    const int v0 = (tid>>4)*8, n0 = (tid&15)*4;

    ull acc[8][2];
    #pragma unroll
    for (int j=0;j<8;j++){ acc[j][0]=0ull; acc[j][1]=0ull; }

    float4 pa0 = *(const float4*)(A + (size_t)ar*HH + ac);
    float4 pa1 = *(const float4*)(A + (size_t)ar*HH + ac + 4);
    float4 pb  = *(const float4*)(Bp + bk*64 + bn);

    const int NT = HH/16;  // 64
    for (int t=0; t<NT; ++t){
        *(float4*)&As[ar][ac]   = pa0;
        *(float4*)&As[ar][ac+4] = pa1;
        *(float4*)&Bs[bk][bn]   = pb;
        __syncthreads();
        if (t+1 < NT){
            const float* An = A + (t+1)*16;
            pa0 = *(const float4*)(An + (size_t)ar*HH + ac);
            pa1 = *(const float4*)(An + (size_t)ar*HH + ac + 4);
            pb  = *(const float4*)(Bp + (size_t)((t+1)*16 + bk)*64 + bn);
        }
        #pragma unroll
        for (int kq=0; kq<4; ++kq){
            float4 av[8];
            #pragma unroll
            for (int j=0;j<8;j++) av[j] = *(const float4*)&As[v0+j][kq*4];
            float4 bv[4];
            #pragma unroll
            for (int kk=0;kk<4;kk++) bv[kk] = *(const float4*)&Bs[kq*4+kk][n0];
            #pragma unroll
            for (int kk=0;kk<4;kk++){
                ull b01 = pk2(((const float*)&bv[kk])[0], ((const float*)&bv[kk])[1]);
                ull b23 = pk2(((const float*)&bv[kk])[2], ((const float*)&bv[kk])[3]);
                #pragma unroll
                for (int j=0;j<8;j++){
                    float a = ((const float*)&av[j])[kk];
                    ull aa = pk2(a, a);
                    ffma2(acc[j][0], aa, b01);
                    ffma2(acc[j][1], aa, b23);
                }
            }
        }
        __syncthreads();
    }

    // epilogue: add bias, transpose through smem, coalesced global writes
    float bo[8];
    #pragma unroll
    for (int j=0;j<8;j++) bo[j] = b_out[vb + v0 + j];
    #pragma unroll
    for (int j=0;j<8;j++){
        float c0,c1,c2,c3;
        upk2(acc[j][0], c0, c1);
        upk2(acc[j][1], c2, c3);
        smemc[(size_t)(n0+0)*128 + v0+j] = c0 + bo[j];
        smemc[(size_t)(n0+1)*128 + v0+j] = c1 + bo[j];
        smemc[(size_t)(n0+2)*128 + v0+j] = c2 + bo[j];
        smemc[(size_t)(n0+3)*128 + v0+j] = c3 + bo[j];
    }
    __syncthreads();
    const int b = tid>>2, q = tid&3;
    float* orow = out + (size_t)b*VV + vb;
    #pragma unroll
    for (int i=0;i<8;i++){
        int f = q*8 + i;
        *(float4*)&orow[f*4] = *(const float4*)&smemc[(size_t)b*128 + f*4];
    }
}

// ---------------------------------------------------------------------------
// Kernel 5: in-place log_softmax per batch row over V=32000. 64 blocks x 1024.
// ---------------------------------------------------------------------------
__global__ __launch_bounds__(1024) void logsoftmax_kernel(float* __restrict__ out)
{
    __shared__ float red[33];
    const int b = blockIdx.x, tid = threadIdx.x, lane = tid & 31, warp = tid >> 5;
    float* row = out + (size_t)b*VV;
    float vals[32];
    float m = -3.0e38f;
    #pragma unroll
    for (int j=0;j<32;j++){
        int idx = tid + j*1024;
        float v = (idx < VV) ? row[idx] : -3.0e38f;
        vals[j] = v;
        m = fmaxf(m, v);
    }
    #pragma unroll
    for (int o=16;o;o>>=1) m = fmaxf(m, __shfl_xor_sync(0xffffffffu, m, o));
    if (lane==0) red[warp] = m;
    __syncthreads();
    if (warp==0){
        float v = red[lane];
        #pragma unroll
        for (int o=16;o;o>>=1) v = fmaxf(v, __shfl_xor_sync(0xffffffffu, v, o));
        if (lane==0) red[32] = v;
    }
    __syncthreads();
    m = red[32];
    __syncthreads();
    float z = 0.f;
    #pragma unroll
    for (int j=0;j<32;j++) z += __expf(vals[j] - m);
    #pragma unroll
    for (int o=16;o;o>>=1) z += __shfl_xor_sync(0xffffffffu, z, o);
    if (lane==0) red[warp] = z;
    __syncthreads();
    if (warp==0){
        float v = red[lane];
        #pragma unroll
        for (int o=16;o;o>>=1) v += __shfl_xor_sync(0xffffffffu, v, o);
        if (lane==0) red[32] = v;
    }
    __syncthreads();
    const float lse = m + logf(red[32]);
    #pragma unroll
    for (int j=0;j<32;j++){
        int idx = tid + j*1024;
        if (idx < VV) row[idx] = vals[j] - lse;
    }
}

// ---------------------------------------------------------------------------
extern "C" void kernel_launch(void* const* d_in, const int* in_sizes, int n_in,
                              void* d_out, int out_size)
{
    const int*   input_batch = (const int*)  d_in[0];
    const float* prev_h      = (const float*)d_in[1];
    const float* prev_c      = (const float*)d_in[2];
    const float* enc         = (const float*)d_in[3];
    const int*   lengths     = (const int*)  d_in[4];
    const float* emb         = (const float*)d_in[5];
    const float* attn_w      = (const float*)d_in[6];
    const float* attn_b      = (const float*)d_in[7];
    const float* W_ih        = (const float*)d_in[8];
    const float* W_hh        = (const float*)d_in[9];
    const float* b_ih        = (const float*)d_in[10];
    const float* b_hh        = (const float*)d_in[11];
    const float* W_out       = (const float*)d_in[12];
    const float* b_out       = (const float*)d_in[13];
    float* out = (float*)d_out;

    attn_kernel<<<64, 256>>>(input_batch, prev_h, enc, emb, attn_w, attn_b, out);
    gates_gemm<<<dim3(32, KSPLIT), 256>>>(W_ih, W_hh);
    lstm_kernel<<<256, 256>>>(prev_c, lengths, b_ih, b_hh, out);
    logits_gemm<<<250, 256>>>(W_out, b_out, out);
    logsoftmax_kernel<<<64, 1024>>>(out);
}

// round 4
// speedup vs baseline: 1.4101x; 1.4101x over previous
#include <cuda_runtime.h>
#include <cuda_bf16.h>
#include <cstdint>
#include <math.h>

// Problem dims
#define BB 64
#define HH 1024
#define SS 128
#define VV 32000
#define KX 2048        // E + H
#define G4 4096        // 4*H
#define KSPLIT 6

// d_out layout (floats)
#define OUT_H1   (64*32000)
#define OUT_C1   (OUT_H1 + 64*1024)
#define OUT_ATTN (OUT_C1 + 64*1024)

// Scratch (no allocation allowed -> device globals)
__device__ __align__(16) float g_xT [KX*BB];          // x^T   (2048 x 64)
__device__ __align__(16) float g_h0T[HH*BB];          // h0^T  (1024 x 64)
__device__ __align__(16) float g_h1T[HH*BB];          // h1^T  (1024 x 64)
__device__ __align__(16) __nv_bfloat16 g_h1bf[BB*HH]; // h1 bf16, [b][k] row-major
__device__ __align__(16) float g_part[KSPLIT*G4*BB];  // gates K-split partials

typedef unsigned long long ull;
__device__ __forceinline__ ull pk2(float x, float y){
    ull r; asm("mov.b64 %0, {%1, %2};" : "=l"(r) : "f"(x), "f"(y)); return r;
}
__device__ __forceinline__ void upk2(ull v, float& x, float& y){
    asm("mov.b64 {%0, %1}, %2;" : "=f"(x), "=f"(y) : "l"(v));
}
__device__ __forceinline__ void ffma2(ull& acc, ull a, ull b){
    asm("fma.rn.f32x2 %0, %1, %2, %0;" : "+l"(acc) : "l"(a), "l"(b));
}
__device__ __forceinline__ void mma16816(float& c0, float& c1, float& c2, float& c3,
                                         uint32_t a0, uint32_t a1, uint32_t a2, uint32_t a3,
                                         uint32_t b0, uint32_t b1){
    asm("mma.sync.aligned.m16n8k16.row.col.f32.bf16.bf16.f32 "
        "{%0,%1,%2,%3},{%4,%5,%6,%7},{%8,%9},{%0,%1,%2,%3};"
        : "+f"(c0), "+f"(c1), "+f"(c2), "+f"(c3)
        : "r"(a0), "r"(a1), "r"(a2), "r"(a3), "r"(b0), "r"(b1));
}
__device__ __forceinline__ void ldm4(uint32_t& r0, uint32_t& r1, uint32_t& r2, uint32_t& r3,
                                     uint32_t addr){
    asm volatile("ldmatrix.sync.aligned.m8n8.x4.shared.b16 {%0,%1,%2,%3}, [%4];"
        : "=r"(r0), "=r"(r1), "=r"(r2), "=r"(r3) : "r"(addr));
}
__device__ __forceinline__ uint32_t cvt2bf(float lo, float hi){
    __nv_bfloat162 h = __floats2bfloat162_rn(lo, hi);   // .x = lo (low 16 bits)
    return *(uint32_t*)&h;
}

// ---------------------------------------------------------------------------
// Kernel 1: attention (scores, softmax, context) + emb gather + transposes
// ---------------------------------------------------------------------------
__global__ void attn_kernel(const int* __restrict__ input_batch, const float* __restrict__ prev_h,
                            const float* __restrict__ enc, const float* __restrict__ emb,
                            const float* __restrict__ attn_w, const float* __restrict__ attn_b,
                            float* __restrict__ out)
{
    __shared__ float sw2[1024];
    __shared__ float sweights[128];
    __shared__ float red[40];
    const int b = blockIdx.x, tid = threadIdx.x, lane = tid & 31, warp = tid >> 5;
    const int tok = input_batch[b];

    float hacc = 0.f;
    for (int i = tid; i < 1024; i += 256){
        float h0v = prev_h[(size_t)b*1024 + i];
        hacc += attn_w[i] * h0v;
        sw2[i] = attn_w[1024 + i];
        g_h0T[(size_t)i*64 + b] = h0v;
        g_xT [(size_t)i*64 + b] = emb[(size_t)tok*1024 + i];
    }
    #pragma unroll
    for (int o=16;o;o>>=1) hacc += __shfl_xor_sync(0xffffffffu, hacc, o);
    if (lane==0) red[warp] = hacc;
    __syncthreads();
    if (tid==0){ float s=0.f; for (int w=0;w<8;w++) s+=red[w]; red[32] = s + attn_b[0]; }
    __syncthreads();
    const float hpb = red[32];

    const float* encb = enc + (size_t)b*SS*HH;
    for (int s = warp; s < 128; s += 8){
        const float* ep = encb + (size_t)s*1024;
        float acc = 0.f;
        #pragma unroll 8
        for (int j=0;j<32;j++){ int i = lane + j*32; acc += ep[i]*sw2[i]; }
        #pragma unroll
        for (int o=16;o;o>>=1) acc += __shfl_xor_sync(0xffffffffu, acc, o);
        if (lane==0) sweights[s] = acc + hpb;
    }
    __syncthreads();

    float sc = (tid<128) ? sweights[tid] : -3.0e38f;
    float m = sc;
    #pragma unroll
    for (int o=16;o;o>>=1) m = fmaxf(m, __shfl_xor_sync(0xffffffffu, m, o));
    if (lane==0) red[warp] = m;
    __syncthreads();
    if (tid==0){ float mm=red[0]; for (int w=1;w<8;w++) mm=fmaxf(mm,red[w]); red[33]=mm; }
    __syncthreads();
    m = red[33];
    float e = (tid<128) ? __expf(sc - m) : 0.f;
    float z = e;
    #pragma unroll
    for (int o=16;o;o>>=1) z += __shfl_xor_sync(0xffffffffu, z, o);
    if (lane==0) red[warp] = z;
    __syncthreads();
    if (tid==0){ float s=0.f; for (int w=0;w<8;w++) s+=red[w]; red[34]=s; }
    __syncthreads();
    const float Z = red[34];
    if (tid < 128){
        float w = e / Z;
        sweights[tid] = w;
        out[OUT_ATTN + b*128 + tid] = w;
    }
    __syncthreads();

    const int h4 = tid*4;
    float4 a4 = {0.f,0.f,0.f,0.f};
    for (int s=0;s<128;s++){
        float w = sweights[s];
        float4 ev = *(const float4*)(encb + (size_t)s*1024 + h4);
        a4.x += w*ev.x; a4.y += w*ev.y; a4.z += w*ev.z; a4.w += w*ev.w;
    }
    g_xT[(size_t)(1024+h4+0)*64 + b] = a4.x;
    g_xT[(size_t)(1024+h4+1)*64 + b] = a4.y;
    g_xT[(size_t)(1024+h4+2)*64 + b] = a4.z;
    g_xT[(size_t)(1024+h4+3)*64 + b] = a4.w;
}

// ---------------------------------------------------------------------------
// Kernel 2: gates GEMM (unchanged FFMA2 path, K-split x 6)
// ---------------------------------------------------------------------------
__global__ __launch_bounds__(256,2) void gates_gemm(const float* __restrict__ W_ih,
                                                    const float* __restrict__ W_hh)
{
    __shared__ __align__(16) float As[128][20];
    __shared__ __align__(16) float Bs[16][64];
    const int tid = threadIdx.x;
    const int g0 = blockIdx.x * 128;
    const int ky = blockIdx.y;
    const int kbase = ky * 512;
    const bool ih = (ky < 4);
    const int lda = ih ? KX : HH;
    const float* A  = ih ? (W_ih + (size_t)g0*KX + kbase)
                         : (W_hh + (size_t)g0*HH + (kbase - KX));
    const float* Bp = ih ? (g_xT + (size_t)kbase*64)
                         : (g_h0T + (size_t)(kbase - KX)*64);

    const int ar = tid>>1, ac = (tid&1)*8;
    const int bk = tid>>4, bn = (tid&15)*4;
    const int v0 = (tid>>4)*8, n0 = (tid&15)*4;

    ull acc[8][2];
    #pragma unroll
    for (int j=0;j<8;j++){ acc[j][0]=0ull; acc[j][1]=0ull; }

    float4 pa0 = *(const float4*)(A + (size_t)ar*lda + ac);
    float4 pa1 = *(const float4*)(A + (size_t)ar*lda + ac + 4);
    float4 pb  = *(const float4*)(Bp + bk*64 + bn);

    const int NT = 512/16;
    for (int t=0; t<NT; ++t){
        *(float4*)&As[ar][ac]   = pa0;
        *(float4*)&As[ar][ac+4] = pa1;
        *(float4*)&Bs[bk][bn]   = pb;
        __syncthreads();
        if (t+1 < NT){
            const float* An = A + (t+1)*16;
            pa0 = *(const float4*)(An + (size_t)ar*lda + ac);
            pa1 = *(const float4*)(An + (size_t)ar*lda + ac + 4);
            pb  = *(const float4*)(Bp + (size_t)((t+1)*16 + bk)*64 + bn);
        }
        #pragma unroll
        for (int kq=0; kq<4; ++kq){
            float4 av[8];
            #pragma unroll
            for (int j=0;j<8;j++) av[j] = *(const float4*)&As[v0+j][kq*4];
            float4 bv[4];
            #pragma unroll
            for (int kk=0;kk<4;kk++) bv[kk] = *(const float4*)&Bs[kq*4+kk][n0];
            #pragma unroll
            for (int kk=0;kk<4;kk++){
                ull b01 = pk2(((const float*)&bv[kk])[0], ((const float*)&bv[kk])[1]);
                ull b23 = pk2(((const float*)&bv[kk])[2], ((const float*)&bv[kk])[3]);
                #pragma unroll
                for (int j=0;j<8;j++){
                    float a = ((const float*)&av[j])[kk];
                    ull aa = pk2(a, a);
                    ffma2(acc[j][0], aa, b01);
                    ffma2(acc[j][1], aa, b23);
                }
            }
        }
        __syncthreads();
    }
    float* P = g_part + ((size_t)ky*G4 + g0)*64;
    #pragma unroll
    for (int j=0;j<8;j++){
        float4 o;
        upk2(acc[j][0], o.x, o.y);
        upk2(acc[j][1], o.z, o.w);
        *(float4*)&P[(size_t)(v0+j)*64 + n0] = o;
    }
}

// ---------------------------------------------------------------------------
// Kernel 3: K-split reduce + biases + LSTM cell (+ bf16 h1 for tensor GEMM)
// ---------------------------------------------------------------------------
__global__ void lstm_kernel(const float* __restrict__ prev_c, const int* __restrict__ lengths,
                            const float* __restrict__ b_ih, const float* __restrict__ b_hh,
                            float* __restrict__ out)
{
    const int id = blockIdx.x*256 + threadIdx.x;   // 0..65535
    const int b = id & 63, h = id >> 6;
    float s[4] = {0.f,0.f,0.f,0.f};
    #pragma unroll
    for (int ky=0; ky<KSPLIT; ++ky){
        const float* P = g_part + (size_t)ky*G4*64;
        #pragma unroll
        for (int g=0; g<4; ++g) s[g] += P[(size_t)(g*1024 + h)*64 + b];
    }
    #pragma unroll
    for (int g=0; g<4; ++g) s[g] += b_ih[g*1024+h] + b_hh[g*1024+h];
    float ig = 1.f/(1.f + __expf(-s[0]));
    float fg = 1.f/(1.f + __expf(-s[1]));
    float gg = tanhf(s[2]);
    float og = 1.f/(1.f + __expf(-s[3]));
    float c0 = prev_c[(size_t)b*HH + h];
    float c1 = fg*c0 + ig*gg;
    float h1 = og*tanhf(c1);
    if (lengths[b] == 0){ c1 = 0.f; h1 = 0.f; }
    out[OUT_H1 + b*HH + h] = h1;
    out[OUT_C1 + b*HH + h] = c1;
    g_h1T[(size_t)h*64 + b] = h1;
    g_h1bf[(size_t)b*HH + h] = __float2bfloat16(h1);
}

// ---------------------------------------------------------------------------
// Kernel 4: logits GEMM via bf16 tensor cores (mma.sync m16n8k16)
// grid 250, 256 threads. Tile M=128(v) x N=64(b), K-chunks of 32.
//   A = W_out rows (fp32 gmem -> bf16 regs -> smem, padded 40-elem rows)
//   B = h1 bf16 ([b][k] row-major in gmem, per-chunk tile in smem)
// Epilogue: +bias, smem transpose, coalesced float4 stores.
// ---------------------------------------------------------------------------
#define LKB 32                       // K per chunk
#define A_PITCH 40                   // bf16 elems per A smem row (80B: ldmatrix conflict-free)
#define B_PITCH 40                   // bf16 elems per B smem row (banks gid*20+tg distinct)
#define A_BUF_BYTES (128*A_PITCH*2)  // 10240
#define B_BUF_BYTES (64*B_PITCH*2)   // 5120
#define SC_PITCH 132                 // epilogue float pitch (conflict-free transpose)

__global__ __launch_bounds__(256) void logits_gemm_mma(const float* __restrict__ W_out,
                                                       const float* __restrict__ b_out,
                                                       float* __restrict__ out)
{
    __shared__ __align__(16) unsigned char sm[64*SC_PITCH*4];   // 33792 >= 30720 pipeline bytes
    const int tid = threadIdx.x, lane = tid & 31, warp = tid >> 5;
    const int gid = lane >> 2, tg = lane & 3;
    const int vb = blockIdx.x * 128;

    const uint32_t smb = (uint32_t)__cvta_generic_to_shared(sm);

    // A staging: thread covers row r = tid>>1, 16 cols at half hh
    const int r  = tid >> 1, hh = tid & 1;
    const float* Ap = W_out + (size_t)(vb + r)*HH + hh*16;
    // B staging: thread covers row t>>2 (batch), 8 bf16 at seg t&3
    const __nv_bfloat16* Bg = g_h1bf + (size_t)(tid>>2)*HH + (tid&3)*8;

    float acc[8][4];
    #pragma unroll
    for (int nt=0; nt<8; nt++){ acc[nt][0]=0.f; acc[nt][1]=0.f; acc[nt][2]=0.f; acc[nt][3]=0.f; }

    // prefetch chunk 0
    float4 pa[4]; uint4 pb;
    #pragma unroll
    for (int j=0;j<4;j++) pa[j] = *(const float4*)(Ap + j*4);
    pb = *(const uint4*)Bg;

    const int NCH = HH / LKB;   // 32
    for (int t=0; t<NCH; ++t){
        const int p = t & 1;
        __nv_bfloat16* AsB = (__nv_bfloat16*)(sm + p*A_BUF_BYTES);
        __nv_bfloat16* BsB = (__nv_bfloat16*)(sm + 2*A_BUF_BYTES + p*B_BUF_BYTES);
        __syncthreads();   // compute on this buffer (from t-2) done
        // store A (convert fp32 -> bf16 pairs)
        #pragma unroll
        for (int j=0;j<4;j++){
            uint32_t lo = cvt2bf(pa[j].x, pa[j].y);
            uint32_t hi = cvt2bf(pa[j].z, pa[j].w);
            *(uint2*)(AsB + r*A_PITCH + hh*16 + j*4) = make_uint2(lo, hi);
        }
        // store B
        *(uint4*)(BsB + (tid>>2)*B_PITCH + (tid&3)*8) = pb;
        __syncthreads();
        // prefetch next chunk
        if (t+1 < NCH){
            const float* An = Ap + (t+1)*LKB;
            #pragma unroll
            for (int j=0;j<4;j++) pa[j] = *(const float4*)(An + j*4);
            pb = *(const uint4*)(Bg + (t+1)*LKB);
        }
        // load B fragments (u32 LDS, conflict-free)
        uint32_t bf[8][2][2];
        #pragma unroll
        for (int nt=0; nt<8; nt++){
            const __nv_bfloat16* bp = BsB + (nt*8 + gid)*B_PITCH + tg*2;
            bf[nt][0][0] = *(const uint32_t*)(bp);
            bf[nt][0][1] = *(const uint32_t*)(bp + 8);
            bf[nt][1][0] = *(const uint32_t*)(bp + 16);
            bf[nt][1][1] = *(const uint32_t*)(bp + 24);
        }
        // compute 2 k-steps x 8 n-tiles
        const uint32_t abase = smb + p*A_BUF_BYTES
                             + (uint32_t)((warp*16 + (lane & 15))*A_PITCH + ((lane>>4)*8)) * 2;
        #pragma unroll
        for (int s=0; s<2; ++s){
            uint32_t a0,a1,a2,a3;
            ldm4(a0,a1,a2,a3, abase + s*32);
            #pragma unroll
            for (int nt=0; nt<8; nt++)
                mma16816(acc[nt][0],acc[nt][1],acc[nt][2],acc[nt][3],
                         a0,a1,a2,a3, bf[nt][s][0], bf[nt][s][1]);
        }
    }
    __syncthreads();   // all compute done before aliasing smem as sc

    // epilogue: + bias, transpose via smem, coalesced writes
    float* scf = (float*)sm;   // [64][SC_PITCH]
    const int m0 = warp*16 + gid, m1 = m0 + 8;
    const float bo0 = b_out[vb + m0];
    const float bo1 = b_out[vb + m1];
    #pragma unroll
    for (int nt=0; nt<8; nt++){
        const int n0 = nt*8 + tg*2;
        scf[(size_t)(n0  )*SC_PITCH + m0] = acc[nt][0] + bo0;
        scf[(size_t)(n0+1)*SC_PITCH + m0] = acc[nt][1] + bo0;
        scf[(size_t)(n0  )*SC_PITCH + m1] = acc[nt][2] + bo1;
        scf[(size_t)(n0+1)*SC_PITCH + m1] = acc[nt][3] + bo1;
    }
    __syncthreads();
    const int b = tid>>2, q = tid&3;
    float* orow = out + (size_t)b*VV + vb;
    #pragma unroll
    for (int i=0;i<8;i++){
        const int f = q*8 + i;
        *(float4*)&orow[f*4] = *(const float4*)&scf[(size_t)b*SC_PITCH + f*4];
    }
}

// ---------------------------------------------------------------------------
// Kernel 5: in-place log_softmax per batch row over V=32000. 64 blocks x 1024.
// ---------------------------------------------------------------------------
__global__ __launch_bounds__(1024) void logsoftmax_kernel(float* __restrict__ out)
{
    __shared__ float red[33];
    const int b = blockIdx.x, tid = threadIdx.x, lane = tid & 31, warp = tid >> 5;
    float* row = out + (size_t)b*VV;
    float vals[32];
    float m = -3.0e38f;
    #pragma unroll
    for (int j=0;j<32;j++){
        int idx = tid + j*1024;
        float v = (idx < VV) ? row[idx] : -3.0e38f;
        vals[j] = v;
        m = fmaxf(m, v);
    }
    #pragma unroll
    for (int o=16;o;o>>=1) m = fmaxf(m, __shfl_xor_sync(0xffffffffu, m, o));
    if (lane==0) red[warp] = m;
    __syncthreads();
    if (warp==0){
        float v = red[lane];
        #pragma unroll
        for (int o=16;o;o>>=1) v = fmaxf(v, __shfl_xor_sync(0xffffffffu, v, o));
        if (lane==0) red[32] = v;
    }
    __syncthreads();
    m = red[32];
    __syncthreads();
    float z = 0.f;
    #pragma unroll
    for (int j=0;j<32;j++) z += __expf(vals[j] - m);
    #pragma unroll
    for (int o=16;o;o>>=1) z += __shfl_xor_sync(0xffffffffu, z, o);
    if (lane==0) red[warp] = z;
    __syncthreads();
    if (warp==0){
        float v = red[lane];
        #pragma unroll
        for (int o=16;o;o>>=1) v += __shfl_xor_sync(0xffffffffu, v, o);
        if (lane==0) red[32] = v;
    }
    __syncthreads();
    const float lse = m + logf(red[32]);
    #pragma unroll
    for (int j=0;j<32;j++){
        int idx = tid + j*1024;
        if (idx < VV) row[idx] = vals[j] - lse;
    }
}

// ---------------------------------------------------------------------------
extern "C" void kernel_launch(void* const* d_in, const int* in_sizes, int n_in,
                              void* d_out, int out_size)
{
    const int*   input_batch = (const int*)  d_in[0];
    const float* prev_h      = (const float*)d_in[1];
    const float* prev_c      = (const float*)d_in[2];
    const float* enc         = (const float*)d_in[3];
    const int*   lengths     = (const int*)  d_in[4];
    const float* emb         = (const float*)d_in[5];
    const float* attn_w      = (const float*)d_in[6];
    const float* attn_b      = (const float*)d_in[7];
    const float* W_ih        = (const float*)d_in[8];
    const float* W_hh        = (const float*)d_in[9];
    const float* b_ih        = (const float*)d_in[10];
    const float* b_hh        = (const float*)d_in[11];
    const float* W_out       = (const float*)d_in[12];
    const float* b_out       = (const float*)d_in[13];
    float* out = (float*)d_out;

    attn_kernel<<<64, 256>>>(input_batch, prev_h, enc, emb, attn_w, attn_b, out);
    gates_gemm<<<dim3(32, KSPLIT), 256>>>(W_ih, W_hh);
    lstm_kernel<<<256, 256>>>(prev_c, lengths, b_ih, b_hh, out);
    logits_gemm_mma<<<250, 256>>>(W_out, b_out, out);
    logsoftmax_kernel<<<64, 1024>>>(out);
}